// round 5
// baseline (speedup 1.0000x reference)
#include <cuda_runtime.h>
#include <math.h>
#include <stdint.h>

#define BB 128
#define RR 4096
#define DD 256
#define NROW (BB * RR)
#define CTAS_PER_B 512   // 4096 rows / 8 rows per CTA

// Static device scratch (no allocations allowed). Zero-initialized at load;
// g_arrive is self-resetting so graph replays see 0 again.
__device__ float g_dot[NROW];
__device__ float g_ss[NROW];
__device__ int   g_arrive[BB];

// ---------------------------------------------------------------------------
// Inline qidx decode: query_rels may be int64 or int32 (jax x64 config).
// If int64 LE with values < 4096, every high 32-bit word is 0. Sampling 64
// odd words (512 B — safe under both interpretations) distinguishes them.
// Executed by warp 0 only; result broadcast via shared.
// ---------------------------------------------------------------------------
__device__ __forceinline__ void decode_qidx_warp0(const void* qr, int b,
                                                  int t, int* s_qidx) {
    if (t < 32) {
        const int* p32 = (const int*)qr;
        int hi = p32[2 * t + 1] | p32[2 * (t + 32) + 1];
        bool is32 = __any_sync(0xFFFFFFFFu, hi != 0);
        if (t == 0) {
            *s_qidx = is32 ? p32[b] : (int)((const long long*)qr)[b];
        }
    }
}

// Block reductions over 256 threads through shared `red`.
__device__ __forceinline__ float bred_sum(float v, float* red) {
    int t = threadIdx.x;
    red[t] = v;
    __syncthreads();
#pragma unroll
    for (int s = 128; s > 0; s >>= 1) {
        if (t < s) red[t] += red[t + s];
        __syncthreads();
    }
    float r = red[0];
    __syncthreads();
    return r;
}
__device__ __forceinline__ float bred_max(float v, float* red) {
    int t = threadIdx.x;
    red[t] = v;
    __syncthreads();
#pragma unroll
    for (int s = 128; s > 0; s >>= 1) {
        if (t < s) red[t] = fmaxf(red[t], red[t + s]);
        __syncthreads();
    }
    float r = red[0];
    __syncthreads();
    return r;
}

// ---------------------------------------------------------------------------
// Single fused kernel:
//  Phase A (every CTA): copy 8 rows + per-row dot(r_i,q_b) and sum-of-squares
//    (warp-per-row, q staged once per CTA in shared, streaming load/store).
//  Phase B (last CTA per batch, via arrive counter): gating + masked softmax
//    + sparse weighted apply. Runs while later batches are still copying and
//    reads this batch's just-written g_dot/g_ss from L2.
//  Key identity: mask = sigmoid((s-thr)*10) > 0.5  <=>  s > thr, so the
//  common path (empty mask) computes no exp at all. The rare path holds no
//  register arrays: it recomputes from shared each pass.
// ---------------------------------------------------------------------------
__global__ void __launch_bounds__(256) fused_kernel(
    const float* __restrict__ in, float* __restrict__ out,
    const void* __restrict__ qr,
    const float* __restrict__ thr_raw, const float* __restrict__ str_raw,
    const float* __restrict__ wscale,  const float* __restrict__ temp_p) {
    __shared__ float qs[DD];
    __shared__ float red[256];
    __shared__ float s_sims[RR];   // 16 KB; later overwritten with coefs
    __shared__ int   s_qidx;
    __shared__ int   s_last;

    int cta = blockIdx.x;
    int b = cta >> 9;            // CTAS_PER_B = 512
    int t = threadIdx.x;

    decode_qidx_warp0(qr, b, t, &s_qidx);
    __syncthreads();
    int qidx = s_qidx;

    // cooperative q stage: 256 threads, 256 floats (L2-hot)
    qs[t] = __ldg(in + ((size_t)b * RR + qidx) * DD + t);
    __syncthreads();

    int warp = t >> 5;
    int lane = t & 31;
    size_t row = (size_t)cta * 8 + warp;

    {
        const float4* rp = (const float4*)(in + row * DD);
        float4* op = (float4*)(out + row * DD);

        float4 a0 = __ldcs(rp + lane);
        float4 a1 = __ldcs(rp + lane + 32);
        __stcs(op + lane, a0);
        __stcs(op + lane + 32, a1);

        float4 q0 = *(const float4*)(qs + 4 * lane);
        float4 q1 = *(const float4*)(qs + 128 + 4 * lane);

        float dot = a0.x * q0.x + a0.y * q0.y + a0.z * q0.z + a0.w * q0.w
                  + a1.x * q1.x + a1.y * q1.y + a1.z * q1.z + a1.w * q1.w;
        float ss  = a0.x * a0.x + a0.y * a0.y + a0.z * a0.z + a0.w * a0.w
                  + a1.x * a1.x + a1.y * a1.y + a1.z * a1.z + a1.w * a1.w;

#pragma unroll
        for (int o = 16; o > 0; o >>= 1) {
            dot += __shfl_xor_sync(0xFFFFFFFFu, dot, o);
            ss  += __shfl_xor_sync(0xFFFFFFFFu, ss, o);
        }
        if (lane == 0) {
            g_dot[row] = dot;
            g_ss[row]  = ss;
            __threadfence();   // release our results before the arrive
        }
    }
    __syncthreads();

    // arrive; the 512th CTA of this batch runs the tail
    if (t == 0) {
        int old = atomicAdd(&g_arrive[b], 1);
        s_last = (old == CTAS_PER_B - 1);
        if (s_last) g_arrive[b] = 0;   // self-reset for graph replay
    }
    __syncthreads();
    if (!s_last) return;
    __threadfence();   // acquire: see all CTAs' g_dot/g_ss stores

    // ---------------- tail (one CTA per batch) ----------------
    float thr = 1.0f / (1.0f + expf(-thr_raw[0]));
    float qn = fmaxf(sqrtf(g_ss[(size_t)b * RR + qidx]), 1e-12f);

    // Pass 1: sims -> shared; count masked (no exp on the common path)
    int lcnt = 0;
#pragma unroll 4
    for (int k = 0; k < 16; k++) {
        int i = t + k * 256;
        size_t idx = (size_t)b * RR + i;
        float nrm = fmaxf(sqrtf(g_ss[idx]), 1e-12f);
        float s = g_dot[idx] / (nrm * qn);
        if (i == qidx) s = -1.0f;
        s_sims[i] = s;
        if (s > thr) lcnt++;
    }

    int total = (int)bred_sum((float)lcnt, red);
    if (total == 0) return;  // phase A already wrote the unchanged q row

    // ---- rare path: mask nonempty (no register arrays; reread shared) ----
    float strength = 0.2f / (1.0f + expf(-str_raw[0]));
    float ws = wscale[0];
    float temp = fminf(fmaxf(temp_p[0], 0.1f), 10.0f);

    float lmax = -1e9f;
    for (int k = 0; k < 16; k++) {
        float s = s_sims[t + k * 256];
        if (s > thr) lmax = fmaxf(lmax, s / temp);
    }
    float m = bred_max(lmax, red);

    float lz = 0.0f;
    for (int k = 0; k < 16; k++) {
        float s = s_sims[t + k * 256];
        if (s > thr) lz += expf(s / temp - m);
        // unmasked entries: exp(-1e9) underflows to exactly 0 in fp32
    }
    float Z = bred_sum(lz, red);

    // coefficient pass: c = softmax * gate * (1 + ws*s); overwrite s_sims
    float lS = 0.0f;
    for (int k = 0; k < 16; k++) {
        int i = t + k * 256;
        float s = s_sims[i];
        float c = 0.0f;
        if (s > thr) {
            float sw = 1.0f / (1.0f + expf(-(s - thr) * 10.0f));
            float w = expf(s / temp - m) / Z;
            c = w * sw * (1.0f + ws * s);
            lS += c;
        }
        s_sims[i] = c;
    }
    float S = bred_sum(lS, red);
    float inv = strength / (S + 1e-8f);

    // sparse weighted sum; thread t = dim index
    float acc = 0.0f;
    for (int j = 0; j < RR; j++) {
        float cf = s_sims[j];
        if (cf != 0.0f) {
            acc += cf * in[((size_t)b * RR + j) * DD + t];
        }
    }

    float q = in[((size_t)b * RR + qidx) * DD + t];
    out[((size_t)b * RR + qidx) * DD + t] = (1.0f - strength) * q + inv * acc;
}

// ---------------------------------------------------------------------------
extern "C" void kernel_launch(void* const* d_in, const int* in_sizes, int n_in,
                              void* d_out, int out_size) {
    const float* reps    = (const float*)d_in[0];
    const void*  qrels   = d_in[1];
    const float* thr_raw = (const float*)d_in[2];
    const float* str_raw = (const float*)d_in[3];
    const float* wscale  = (const float*)d_in[4];
    const float* temp_p  = (const float*)d_in[5];
    float* out = (float*)d_out;

    fused_kernel<<<NROW / 8, 256>>>(reps, out, qrels,
                                    thr_raw, str_raw, wscale, temp_p);
}

// round 6
// speedup vs baseline: 1.1847x; 1.1847x over previous
#include <cuda_runtime.h>
#include <math.h>
#include <stdint.h>

#define BB 128
#define RR 4096
#define DD 256
#define NROW (BB * RR)

// Static device scratch (no allocations allowed). g_cnt zero-init at load
// and self-resetting each run (tail kernel resets it).
__device__ float g_sims[NROW];
__device__ int   g_cnt[BB];

// ---------------------------------------------------------------------------
// Inline qidx decode: query_rels may be int64 or int32 (jax x64 config).
// If int64 LE with values < 4096, every high 32-bit word is 0. Sampling 64
// odd words (512 B — safe under both interpretations) distinguishes them.
// Executed by warp 0 only; result broadcast via shared.
// ---------------------------------------------------------------------------
__device__ __forceinline__ void decode_qidx_warp0(const void* qr, int b,
                                                  int t, int* s_qidx) {
    if (t < 32) {
        const int* p32 = (const int*)qr;
        int hi = p32[2 * t + 1] | p32[2 * (t + 32) + 1];
        bool is32 = __any_sync(0xFFFFFFFFu, hi != 0);
        if (t == 0) {
            *s_qidx = is32 ? p32[b] : (int)((const long long*)qr)[b];
        }
    }
}

// ---------------------------------------------------------------------------
// Kernel 1: fused copy + FINISHED similarity per row.
// One warp per row, 8 rows per 256-thread CTA. q staged once per CTA in
// shared; qn (query norm) computed per CTA with one 256-wide reduce. Each
// warp stores s = dot/(nrm*qn) (self forced to -1) to g_sims, and the CTA
// bumps g_cnt[b] ONLY if it saw any s > thr (never, for this data
// distribution -> zero global atomics on the common path). No fences: the
// kernel boundary orders g_sims/g_cnt against the tail kernel.
// ---------------------------------------------------------------------------
__global__ void __launch_bounds__(256) fuse_copy_sims_kernel(
    const float* __restrict__ in, float* __restrict__ out,
    const void* __restrict__ qr, const float* __restrict__ thr_raw) {
    __shared__ float qs[DD];
    __shared__ float red[256];
    __shared__ int   s_qidx;
    __shared__ int   s_cnt;

    int cta = blockIdx.x;
    int b = cta >> 9;            // 512 CTAs per batch
    int t = threadIdx.x;

    decode_qidx_warp0(qr, b, t, &s_qidx);
    if (t == 0) s_cnt = 0;
    __syncthreads();
    int qidx = s_qidx;

    // cooperative q stage (L2-hot) + query-norm reduce
    float qv = __ldg(in + ((size_t)b * RR + qidx) * DD + t);
    qs[t] = qv;
    red[t] = qv * qv;
    __syncthreads();
#pragma unroll
    for (int s = 128; s > 0; s >>= 1) {
        if (t < s) red[t] += red[t + s];
        __syncthreads();
    }
    float qn = fmaxf(sqrtf(red[0]), 1e-12f);
    float thr = 1.0f / (1.0f + expf(-thr_raw[0]));

    int warp = t >> 5;
    int lane = t & 31;
    size_t row = (size_t)cta * 8 + warp;

    const float4* rp = (const float4*)(in + row * DD);
    float4* op = (float4*)(out + row * DD);

    float4 a0 = __ldcs(rp + lane);
    float4 a1 = __ldcs(rp + lane + 32);
    __stcs(op + lane, a0);
    __stcs(op + lane + 32, a1);

    float4 q0 = *(const float4*)(qs + 4 * lane);
    float4 q1 = *(const float4*)(qs + 128 + 4 * lane);

    float dot = a0.x * q0.x + a0.y * q0.y + a0.z * q0.z + a0.w * q0.w
              + a1.x * q1.x + a1.y * q1.y + a1.z * q1.z + a1.w * q1.w;
    float ss  = a0.x * a0.x + a0.y * a0.y + a0.z * a0.z + a0.w * a0.w
              + a1.x * a1.x + a1.y * a1.y + a1.z * a1.z + a1.w * a1.w;

#pragma unroll
    for (int o = 16; o > 0; o >>= 1) {
        dot += __shfl_xor_sync(0xFFFFFFFFu, dot, o);
        ss  += __shfl_xor_sync(0xFFFFFFFFu, ss, o);
    }
    if (lane == 0) {
        float nrm = fmaxf(sqrtf(ss), 1e-12f);
        float s = dot / (nrm * qn);
        if (row == (size_t)b * RR + (size_t)qidx - (size_t)b * RR + (size_t)b * RR
            && false) {}
        if ((int)(row - (size_t)b * RR) == qidx) s = -1.0f;
        g_sims[row] = s;
        if (s > thr) atomicAdd(&s_cnt, 1);
    }
    __syncthreads();
    if (t == 0 && s_cnt > 0) atomicAdd(&g_cnt[b], s_cnt);
}

// Block reductions over 256 threads through shared `red`.
__device__ __forceinline__ float bred_sum(float v, float* red) {
    int t = threadIdx.x;
    red[t] = v;
    __syncthreads();
#pragma unroll
    for (int s = 128; s > 0; s >>= 1) {
        if (t < s) red[t] += red[t + s];
        __syncthreads();
    }
    float r = red[0];
    __syncthreads();
    return r;
}
__device__ __forceinline__ float bred_max(float v, float* red) {
    int t = threadIdx.x;
    red[t] = v;
    __syncthreads();
#pragma unroll
    for (int s = 128; s > 0; s >>= 1) {
        if (t < s) red[t] = fmaxf(red[t], red[t + s]);
        __syncthreads();
    }
    float r = red[0];
    __syncthreads();
    return r;
}

// ---------------------------------------------------------------------------
// Kernel 2: per-batch tail. Common path: one load of g_cnt[b] -> reset,
// exit (the copy already wrote the unchanged q row). Rare path: masked
// softmax + coefficients + sparse weighted apply from g_sims.
// ---------------------------------------------------------------------------
__global__ void __launch_bounds__(256) tail_kernel(
    const float* __restrict__ in, float* __restrict__ out,
    const void* __restrict__ qr,
    const float* __restrict__ thr_raw, const float* __restrict__ str_raw,
    const float* __restrict__ wscale,  const float* __restrict__ temp_p) {
    __shared__ float red[256];
    __shared__ float s_cf[RR];   // 16 KB
    __shared__ int   s_qidx;
    int b = blockIdx.x;
    int t = threadIdx.x;

    if (g_cnt[b] == 0) return;          // common path: nothing to do
    if (t == 0) g_cnt[b] = 0;           // reset for next graph replay

    decode_qidx_warp0(qr, b, t, &s_qidx);
    __syncthreads();
    int qidx = s_qidx;

    float thr = 1.0f / (1.0f + expf(-thr_raw[0]));
    float strength = 0.2f / (1.0f + expf(-str_raw[0]));
    float ws = wscale[0];
    float temp = fminf(fmaxf(temp_p[0], 0.1f), 10.0f);

    // stage sims into shared
#pragma unroll 4
    for (int k = 0; k < 16; k++) {
        int i = t + k * 256;
        s_cf[i] = g_sims[(size_t)b * RR + i];
    }
    __syncthreads();

    float lmax = -1e9f;
    for (int k = 0; k < 16; k++) {
        float s = s_cf[t + k * 256];
        if (s > thr) lmax = fmaxf(lmax, s / temp);
    }
    float m = bred_max(lmax, red);

    float lz = 0.0f;
    for (int k = 0; k < 16; k++) {
        float s = s_cf[t + k * 256];
        if (s > thr) lz += expf(s / temp - m);
        // unmasked entries: exp(-1e9) underflows to exactly 0 in fp32
    }
    float Z = bred_sum(lz, red);

    // coefficient pass: c = softmax * gate * (1 + ws*s); overwrite s_cf
    float lS = 0.0f;
    __syncthreads();
    for (int k = 0; k < 16; k++) {
        int i = t + k * 256;
        float s = s_cf[i];
        float c = 0.0f;
        if (s > thr) {
            float sw = 1.0f / (1.0f + expf(-(s - thr) * 10.0f));
            float w = expf(s / temp - m) / Z;
            c = w * sw * (1.0f + ws * s);
            lS += c;
        }
        s_cf[i] = c;
    }
    float S = bred_sum(lS, red);
    float inv = strength / (S + 1e-8f);

    // sparse weighted sum; thread t = dim index
    float acc = 0.0f;
    for (int j = 0; j < RR; j++) {
        float cf = s_cf[j];
        if (cf != 0.0f) {
            acc += cf * in[((size_t)b * RR + j) * DD + t];
        }
    }

    float q = in[((size_t)b * RR + qidx) * DD + t];
    out[((size_t)b * RR + qidx) * DD + t] = (1.0f - strength) * q + inv * acc;
}

// ---------------------------------------------------------------------------
extern "C" void kernel_launch(void* const* d_in, const int* in_sizes, int n_in,
                              void* d_out, int out_size) {
    const float* reps    = (const float*)d_in[0];
    const void*  qrels   = d_in[1];
    const float* thr_raw = (const float*)d_in[2];
    const float* str_raw = (const float*)d_in[3];
    const float* wscale  = (const float*)d_in[4];
    const float* temp_p  = (const float*)d_in[5];
    float* out = (float*)d_out;

    fuse_copy_sims_kernel<<<NROW / 8, 256>>>(reps, out, qrels, thr_raw);

    tail_kernel<<<BB, 256>>>(reps, out, qrels,
                             thr_raw, str_raw, wscale, temp_p);
}

// round 7
// speedup vs baseline: 1.2693x; 1.0714x over previous
#include <cuda_runtime.h>
#include <math.h>
#include <stdint.h>

#define BB 128
#define RR 4096
#define DD 256
#define NROW (BB * RR)

// Static device scratch (no allocations allowed). g_cnt is zero-initialized
// at load and self-resetting (tail kernel resets it each run).
__device__ float g_sims[NROW];
__device__ int   g_cnt[BB];

// ---------------------------------------------------------------------------
// Inline qidx decode: query_rels may be int64 or int32 (jax x64 config).
// If int64 LE with values < 4096, every high 32-bit word is 0. Sampling 64
// odd words (512 B — safe under both interpretations) distinguishes them.
// Executed by warp 0 only; result broadcast via shared.
// ---------------------------------------------------------------------------
__device__ __forceinline__ void decode_qidx_warp0(const void* qr, int b,
                                                  int t, int* s_qidx) {
    if (t < 32) {
        const int* p32 = (const int*)qr;
        int hi = p32[2 * t + 1] | p32[2 * (t + 32) + 1];
        bool is32 = __any_sync(0xFFFFFFFFu, hi != 0);
        if (t == 0) {
            *s_qidx = is32 ? p32[b] : (int)((const long long*)qr)[b];
        }
    }
}

// ---------------------------------------------------------------------------
// Kernel 1: fused copy + FINISHED similarity per row.
// One warp per row, 8 rows per 256-thread CTA (R4-proven sync structure:
// exactly two __syncthreads, then pure streaming). Each warp holds the FULL
// q row in registers (q0,q1 across 32 lanes), so the query norm qq rides
// the existing shuffle reduction as a third accumulator — no block reduce,
// no extra syncs. Lane 0 computes s = dot/(max(||r||,eps)*max(||q||,eps)),
// stores it, and bumps g_cnt[b] only when s clears the threshold (with a
// conservative margin; never taken for this data distribution -> zero
// global atomics on the common path). The kernel boundary orders
// g_sims/g_cnt against the tail kernel — no fences anywhere.
// ---------------------------------------------------------------------------
__global__ void __launch_bounds__(256) fuse_copy_sims_kernel(
    const float* __restrict__ in, float* __restrict__ out,
    const void* __restrict__ qr, const float* __restrict__ thr_raw) {
    __shared__ float qs[DD];
    __shared__ int   s_qidx;

    int cta = blockIdx.x;
    int b = cta >> 9;            // 512 CTAs per batch
    int t = threadIdx.x;

    decode_qidx_warp0(qr, b, t, &s_qidx);
    __syncthreads();
    int qidx = s_qidx;

    // cooperative q stage: 256 threads, 256 floats (L2-hot)
    qs[t] = __ldg(in + ((size_t)b * RR + qidx) * DD + t);
    __syncthreads();

    int warp = t >> 5;
    int lane = t & 31;
    size_t row = (size_t)cta * 8 + warp;

    const float4* rp = (const float4*)(in + row * DD);
    float4* op = (float4*)(out + row * DD);

    float4 a0 = __ldcs(rp + lane);
    float4 a1 = __ldcs(rp + lane + 32);
    __stcs(op + lane, a0);
    __stcs(op + lane + 32, a1);

    float4 q0 = *(const float4*)(qs + 4 * lane);
    float4 q1 = *(const float4*)(qs + 128 + 4 * lane);

    float dot = a0.x * q0.x + a0.y * q0.y + a0.z * q0.z + a0.w * q0.w
              + a1.x * q1.x + a1.y * q1.y + a1.z * q1.z + a1.w * q1.w;
    float ss  = a0.x * a0.x + a0.y * a0.y + a0.z * a0.z + a0.w * a0.w
              + a1.x * a1.x + a1.y * a1.y + a1.z * a1.z + a1.w * a1.w;
    float qq  = q0.x * q0.x + q0.y * q0.y + q0.z * q0.z + q0.w * q0.w
              + q1.x * q1.x + q1.y * q1.y + q1.z * q1.z + q1.w * q1.w;

#pragma unroll
    for (int o = 16; o > 0; o >>= 1) {
        dot += __shfl_xor_sync(0xFFFFFFFFu, dot, o);
        ss  += __shfl_xor_sync(0xFFFFFFFFu, ss, o);
        qq  += __shfl_xor_sync(0xFFFFFFFFu, qq, o);
    }
    if (lane == 0) {
        float nrm = fmaxf(sqrtf(ss), 1e-12f);
        float qn  = fmaxf(sqrtf(qq), 1e-12f);
        float s = dot / (nrm * qn);
        if ((int)(row & (RR - 1)) == qidx) s = -1.0f;
        g_sims[row] = s;
        float thr = 1.0f / (1.0f + expf(-thr_raw[0]));
        if (s > thr - 1e-4f) atomicAdd(&g_cnt[b], 1);  // conservative; rare
    }
}

// Block reductions over 256 threads through shared `red`.
__device__ __forceinline__ float bred_sum(float v, float* red) {
    int t = threadIdx.x;
    red[t] = v;
    __syncthreads();
#pragma unroll
    for (int s = 128; s > 0; s >>= 1) {
        if (t < s) red[t] += red[t + s];
        __syncthreads();
    }
    float r = red[0];
    __syncthreads();
    return r;
}
__device__ __forceinline__ float bred_max(float v, float* red) {
    int t = threadIdx.x;
    red[t] = v;
    __syncthreads();
#pragma unroll
    for (int s = 128; s > 0; s >>= 1) {
        if (t < s) red[t] = fmaxf(red[t], red[t + s]);
        __syncthreads();
    }
    float r = red[0];
    __syncthreads();
    return r;
}

// ---------------------------------------------------------------------------
// Kernel 2: per-batch tail. Common path: one load of g_cnt[b] -> exit
// (the copy already wrote the unchanged q row); whole kernel is launch-
// latency bound (~4us). Rare path: exact recount (guards against the
// conservative margin in kernel 1), masked softmax + coefficients +
// sparse weighted apply from g_sims.
// ---------------------------------------------------------------------------
__global__ void __launch_bounds__(256) tail_kernel(
    const float* __restrict__ in, float* __restrict__ out,
    const void* __restrict__ qr,
    const float* __restrict__ thr_raw, const float* __restrict__ str_raw,
    const float* __restrict__ wscale,  const float* __restrict__ temp_p) {
    __shared__ float red[256];
    __shared__ float s_cf[RR];   // 16 KB
    __shared__ int   s_qidx;
    int b = blockIdx.x;
    int t = threadIdx.x;

    int cnt = g_cnt[b];
    __syncthreads();             // all reads done before t0 resets
    if (cnt == 0) return;        // common path: nothing to do
    if (t == 0) g_cnt[b] = 0;    // reset for next graph replay

    decode_qidx_warp0(qr, b, t, &s_qidx);
    __syncthreads();
    int qidx = s_qidx;

    float thr = 1.0f / (1.0f + expf(-thr_raw[0]));
    float strength = 0.2f / (1.0f + expf(-str_raw[0]));
    float ws = wscale[0];
    float temp = fminf(fmaxf(temp_p[0], 0.1f), 10.0f);

    // stage sims into shared + exact recount
    int lcnt = 0;
#pragma unroll 4
    for (int k = 0; k < 16; k++) {
        int i = t + k * 256;
        float s = g_sims[(size_t)b * RR + i];
        s_cf[i] = s;
        if (s > thr) lcnt++;
    }
    int total = (int)bred_sum((float)lcnt, red);
    if (total == 0) return;      // margin-induced false positive: row is fine

    float lmax = -1e9f;
    for (int k = 0; k < 16; k++) {
        float s = s_cf[t + k * 256];
        if (s > thr) lmax = fmaxf(lmax, s / temp);
    }
    float m = bred_max(lmax, red);

    float lz = 0.0f;
    for (int k = 0; k < 16; k++) {
        float s = s_cf[t + k * 256];
        if (s > thr) lz += expf(s / temp - m);
        // unmasked entries: exp(-1e9) underflows to exactly 0 in fp32
    }
    float Z = bred_sum(lz, red);

    // coefficient pass: c = softmax * gate * (1 + ws*s); overwrite s_cf
    float lS = 0.0f;
    for (int k = 0; k < 16; k++) {
        int i = t + k * 256;
        float s = s_cf[i];
        float c = 0.0f;
        if (s > thr) {
            float sw = 1.0f / (1.0f + expf(-(s - thr) * 10.0f));
            float w = expf(s / temp - m) / Z;
            c = w * sw * (1.0f + ws * s);
            lS += c;
        }
        s_cf[i] = c;
    }
    float S = bred_sum(lS, red);
    float inv = strength / (S + 1e-8f);

    // sparse weighted sum; thread t = dim index
    float acc = 0.0f;
    for (int j = 0; j < RR; j++) {
        float cf = s_cf[j];
        if (cf != 0.0f) {
            acc += cf * in[((size_t)b * RR + j) * DD + t];
        }
    }

    float q = in[((size_t)b * RR + qidx) * DD + t];
    out[((size_t)b * RR + qidx) * DD + t] = (1.0f - strength) * q + inv * acc;
}

// ---------------------------------------------------------------------------
extern "C" void kernel_launch(void* const* d_in, const int* in_sizes, int n_in,
                              void* d_out, int out_size) {
    const float* reps    = (const float*)d_in[0];
    const void*  qrels   = d_in[1];
    const float* thr_raw = (const float*)d_in[2];
    const float* str_raw = (const float*)d_in[3];
    const float* wscale  = (const float*)d_in[4];
    const float* temp_p  = (const float*)d_in[5];
    float* out = (float*)d_out;

    fuse_copy_sims_kernel<<<NROW / 8, 256>>>(reps, out, qrels, thr_raw);

    tail_kernel<<<BB, 256>>>(reps, out, qrels,
                             thr_raw, str_raw, wscale, temp_p);
}